// round 6
// baseline (speedup 1.0000x reference)
#include <cuda_runtime.h>
#include <cuda_fp16.h>
#include <mma.h>

using namespace nvcuda;

// ---------------- problem constants ----------------
constexpr int B_  = 8;
constexpr int M_  = 8;
constexpr int D_  = 512;
constexpr int DH_ = 64;
constexpr int O_  = 64;
constexpr int SS_ = 72;    // M + O

constexpr int NTT = B_ * 512 * M_;  // 32768 temporal rows
constexpr int NSS = B_ * SS_;       // 576 ss rows

constexpr long long SZ_TOUT = (long long)B_ * 513 * M_ * D_;
constexpr long long SZ_OOUT = (long long)B_ * O_ * D_;
constexpr long long SZ_TATT = (long long)B_ * 8 * 512 * M_ * SS_;
constexpr long long OFF_OOUT = SZ_TOUT;
constexpr long long OFF_TATT = OFF_OOUT + SZ_OOUT;
constexpr long long OFF_OATT = OFF_TATT + SZ_TATT;

// ---------------- scratch (fp16: attention rounds to fp16 anyway) ----------------
__device__ __half g_tt[3][(size_t)NTT * D_];   // Qtt, Ktt, Vtt (no bias)
__device__ __half g_ss[3][(size_t)NSS * D_];   // Qss, Kss, Vss (no bias)

// ============================================================================
// Projection GEMM v6: fp16 WMMA (m16n16k16), fp32 accumulate, fp16 output.
// BM=256 BN=128 BK=32, 512 threads / 16 warps (4x4), warp = 64x32.
// Double-buffered smem. C[r,n] = sum_d X[r,d]*W[n,d]; bias deferred.
// ============================================================================
constexpr int P_BM = 256, P_BN = 128, P_BK = 32, P_LD = P_BK + 8;  // halves
constexpr int P_BUF = (P_BM + P_BN) * P_LD;                        // halves per buffer
constexpr int SMEM_PROJ = 2 * P_BUF * 2;                           // 61440 bytes

template<int MODE>
__global__ __launch_bounds__(512) void proj_gemm(
    const float* __restrict__ Xt, const float* __restrict__ Xo,
    const float* __restrict__ Wq, const float* __restrict__ Wk,
    const float* __restrict__ Wv)
{
    extern __shared__ __half smh[];

    const int tid  = threadIdx.x;
    const int warp = tid >> 5;
    const int lane = tid & 31;
    const int wr   = warp >> 2;
    const int wc   = warp & 3;
    const int tm   = blockIdx.x;
    const int tn   = blockIdx.y;
    const int mat  = blockIdx.z;

    const float* W   = (mat == 0) ? Wq : ((mat == 1) ? Wk : Wv);
    __half*      Out = (MODE == 0) ? g_tt[mat] : g_ss[mat];
    const int  Mrows = (MODE == 0) ? NTT : NSS;

    const int ar = tid >> 3;
    const int ac = (tid & 7) * 4;

    wmma::fragment<wmma::accumulator, 16, 16, 16, float> acc[4][2];
#pragma unroll
    for (int i = 0; i < 4; i++)
#pragma unroll
        for (int j = 0; j < 2; j++) wmma::fill_fragment(acc[i][j], 0.0f);

    float4 ra[4], rb[2];

    auto ldg = [&](int k0) {
#pragma unroll
        for (int i = 0; i < 4; i++) {
            int r  = ar + i * 64;
            int gr = tm * P_BM + r;
            float4 v = make_float4(0.f, 0.f, 0.f, 0.f);
            if (MODE == 0) {
                const float* src = Xt + (size_t)(gr + ((gr >> 12) << 3) + 8) * D_;
                v = *reinterpret_cast<const float4*>(src + k0 + ac);
            } else if (gr < NSS) {
                int bb = gr / SS_;
                int jj = gr - bb * SS_;
                const float* src = (jj < M_) ? (Xt + (size_t)(bb * 4104 + jj) * D_)
                                             : (Xo + (size_t)(bb * O_ + jj - M_) * D_);
                v = *reinterpret_cast<const float4*>(src + k0 + ac);
            }
            ra[i] = v;
        }
#pragma unroll
        for (int i = 0; i < 2; i++) {
            int r = ar + i * 64;
            rb[i] = *reinterpret_cast<const float4*>(W + (size_t)(tn * P_BN + r) * D_ + k0 + ac);
        }
    };

    auto sts = [&](int buf) {
        __half* As = smh + buf * P_BUF;
        __half* Bs = As + P_BM * P_LD;
#pragma unroll
        for (int i = 0; i < 4; i++) {
            *reinterpret_cast<__half2*>(&As[(ar + i * 64) * P_LD + ac])     = __floats2half2_rn(ra[i].x, ra[i].y);
            *reinterpret_cast<__half2*>(&As[(ar + i * 64) * P_LD + ac + 2]) = __floats2half2_rn(ra[i].z, ra[i].w);
        }
#pragma unroll
        for (int i = 0; i < 2; i++) {
            *reinterpret_cast<__half2*>(&Bs[(ar + i * 64) * P_LD + ac])     = __floats2half2_rn(rb[i].x, rb[i].y);
            *reinterpret_cast<__half2*>(&Bs[(ar + i * 64) * P_LD + ac + 2]) = __floats2half2_rn(rb[i].z, rb[i].w);
        }
    };

    ldg(0);
    sts(0);
    __syncthreads();

    for (int kt = 0; kt < D_ / P_BK; kt++) {
        if (kt + 1 < D_ / P_BK) ldg((kt + 1) * P_BK);

        const __half* As = smh + (kt & 1) * P_BUF;
        const __half* Bs = As + P_BM * P_LD;
#pragma unroll
        for (int kk = 0; kk < P_BK; kk += 16) {
            wmma::fragment<wmma::matrix_a, 16, 16, 16, __half, wmma::row_major> af[4];
            wmma::fragment<wmma::matrix_b, 16, 16, 16, __half, wmma::col_major> bf[2];
#pragma unroll
            for (int i = 0; i < 4; i++)
                wmma::load_matrix_sync(af[i], &As[(wr * 64 + i * 16) * P_LD + kk], P_LD);
#pragma unroll
            for (int j = 0; j < 2; j++)
                wmma::load_matrix_sync(bf[j], &Bs[(wc * 32 + j * 16) * P_LD + kk], P_LD);
#pragma unroll
            for (int i = 0; i < 4; i++)
#pragma unroll
                for (int j = 0; j < 2; j++)
                    wmma::mma_sync(acc[i][j], af[i], bf[j], acc[i][j]);
        }
        if (kt + 1 < D_ / P_BK) sts((kt + 1) & 1);
        __syncthreads();
    }

    // ---- epilogue: fp32 fragments -> smem patch -> fp16 gmem ----
    {
        float* pw = reinterpret_cast<float*>(smh) + warp * (16 * 20);
        const int pr = lane >> 1;
        const int pc = (lane & 1) * 8;
#pragma unroll
        for (int i = 0; i < 4; i++) {
            int row0 = tm * P_BM + wr * 64 + i * 16;
            if (row0 + 16 > Mrows) continue;
#pragma unroll
            for (int j = 0; j < 2; j++) {
                wmma::store_matrix_sync(pw, acc[i][j], 20, wmma::mem_row_major);
                __syncwarp();
                float4 a = *reinterpret_cast<const float4*>(&pw[pr * 20 + pc]);
                float4 b = *reinterpret_cast<const float4*>(&pw[pr * 20 + pc + 4]);
                union { uint4 u; __half2 h[4]; } pk;
                pk.h[0] = __floats2half2_rn(a.x, a.y);
                pk.h[1] = __floats2half2_rn(a.z, a.w);
                pk.h[2] = __floats2half2_rn(b.x, b.y);
                pk.h[3] = __floats2half2_rn(b.z, b.w);
                *reinterpret_cast<uint4*>(
                    &Out[(size_t)(row0 + pr) * D_ + tn * P_BN + wc * 32 + j * 16 + pc]) = pk.u;
                __syncwarp();
            }
        }
    }
}

// ============================================================================
// Temporal attention v6 — fp16 WMMA, fp16 scratch reads.
// Block = (b, h, chunk of 64 l). 256 threads / 8 warps.
// ============================================================================
constexpr int ST  = 72;    // halves stride for Q/K/V tiles
constexpr int SPD = 132;   // floats stride for S
constexpr int PHD = 136;   // halves stride for P
constexpr int SMEM_ATT =
    64 * ST * 2 + 128 * ST * 2 + 128 * ST * 2
  + 64 * SPD * 4 + 64 * PHD * 2 + 3 * 64 * 4;

__global__ __launch_bounds__(256) void temporal_attn_kernel(
    const float* __restrict__ bq, const float* __restrict__ bk,
    const float* __restrict__ bv, float* __restrict__ out)
{
    extern __shared__ char smc[];
    __half* Ql  = reinterpret_cast<__half*>(smc);
    __half* Kst = Ql  + 64 * ST;
    __half* Vst = Kst + 128 * ST;
    float*  SP  = reinterpret_cast<float*>(Vst + 128 * ST);
    __half* Ph  = reinterpret_cast<__half*>(SP + 64 * SPD);
    float*  bqs = reinterpret_cast<float*>(Ph + 64 * PHD);
    float*  bks = bqs + 64;
    float*  bvs = bks + 64;

    const int tid  = threadIdx.x;
    const int warp = tid >> 5;
    const int lane = tid & 31;
    const int b  = blockIdx.z, h = blockIdx.y;
    const int l0 = blockIdx.x * 64;
    const int cb = h * DH_;
    const int c4 = (tid & 15) * 4;

    if (tid < 64) {
        bqs[tid] = bq[cb + tid];
        bks[tid] = bk[cb + tid];
        bvs[tid] = bv[cb + tid];
    }
    __syncthreads();

    const __half2 bq01 = __floats2half2_rn(bqs[c4],     bqs[c4 + 1]);
    const __half2 bq23 = __floats2half2_rn(bqs[c4 + 2], bqs[c4 + 3]);
    const __half2 bk01 = __floats2half2_rn(bks[c4],     bks[c4 + 1]);
    const __half2 bk23 = __floats2half2_rn(bks[c4 + 2], bks[c4 + 3]);
    const __half2 bv01 = __floats2half2_rn(bvs[c4],     bvs[c4 + 1]);
    const __half2 bv23 = __floats2half2_rn(bvs[c4 + 2], bvs[c4 + 3]);

    // ---- stage Kts/Vts once into rows 64..127 ----
#pragma unroll
    for (int i = 0; i < 4; i++) {
        int idx = tid + i * 256;
        int o = idx >> 4;
        size_t srow = (size_t)(b * SS_ + 8 + o) * D_ + cb + c4;
        uint2 kr = *reinterpret_cast<const uint2*>(&g_ss[1][srow]);
        __half2 k01 = __hadd2(*reinterpret_cast<__half2*>(&kr.x), bk01);
        __half2 k23 = __hadd2(*reinterpret_cast<__half2*>(&kr.y), bk23);
        *reinterpret_cast<__half2*>(&Kst[(64 + o) * ST + c4])     = k01;
        *reinterpret_cast<__half2*>(&Kst[(64 + o) * ST + c4 + 2]) = k23;
        uint2 vr = *reinterpret_cast<const uint2*>(&g_ss[2][srow]);
        __half2 v01 = __hadd2(*reinterpret_cast<__half2*>(&vr.x), bv01);
        __half2 v23 = __hadd2(*reinterpret_cast<__half2*>(&vr.y), bv23);
        *reinterpret_cast<__half2*>(&Vst[(64 + o) * ST + c4])     = v01;
        *reinterpret_cast<__half2*>(&Vst[(64 + o) * ST + c4 + 2]) = v23;
    }
    __syncthreads();

    for (int li0 = 0; li0 < 64; li0 += 8) {
        const size_t rbase = (size_t)b * 4096 + (size_t)(l0 + li0) * 8;

        // ---- stage Ql / Kl / Vl (rows 0..63) ----
#pragma unroll
        for (int i = 0; i < 4; i++) {
            int idx = tid + i * 256;
            int r = idx >> 4;
            size_t off = (rbase + r) * D_ + cb + c4;
            uint2 qr = *reinterpret_cast<const uint2*>(&g_tt[0][off]);
            *reinterpret_cast<__half2*>(&Ql[r * ST + c4])     = __hadd2(*reinterpret_cast<__half2*>(&qr.x), bq01);
            *reinterpret_cast<__half2*>(&Ql[r * ST + c4 + 2]) = __hadd2(*reinterpret_cast<__half2*>(&qr.y), bq23);
            uint2 kr = *reinterpret_cast<const uint2*>(&g_tt[1][off]);
            *reinterpret_cast<__half2*>(&Kst[r * ST + c4])     = __hadd2(*reinterpret_cast<__half2*>(&kr.x), bk01);
            *reinterpret_cast<__half2*>(&Kst[r * ST + c4 + 2]) = __hadd2(*reinterpret_cast<__half2*>(&kr.y), bk23);
            uint2 vr = *reinterpret_cast<const uint2*>(&g_tt[2][off]);
            *reinterpret_cast<__half2*>(&Vst[r * ST + c4])     = __hadd2(*reinterpret_cast<__half2*>(&vr.x), bv01);
            *reinterpret_cast<__half2*>(&Vst[r * ST + c4 + 2]) = __hadd2(*reinterpret_cast<__half2*>(&vr.y), bv23);
        }
        __syncthreads();

        // ---- S = Q . Kst^T (64x128) ----
        {
            const int rt = warp >> 1;
            const int ct0 = (warp & 1) * 4;
            wmma::fragment<wmma::accumulator, 16, 16, 16, float> sacc[4];
#pragma unroll
            for (int j = 0; j < 4; j++) wmma::fill_fragment(sacc[j], 0.0f);
#pragma unroll
            for (int ks = 0; ks < 4; ks++) {
                wmma::fragment<wmma::matrix_a, 16, 16, 16, __half, wmma::row_major> af;
                wmma::load_matrix_sync(af, &Ql[(rt * 16) * ST + ks * 16], ST);
#pragma unroll
                for (int j = 0; j < 4; j++) {
                    wmma::fragment<wmma::matrix_b, 16, 16, 16, __half, wmma::col_major> bf;
                    wmma::load_matrix_sync(bf, &Kst[((ct0 + j) * 16) * ST + ks * 16], ST);
                    wmma::mma_sync(sacc[j], af, bf, sacc[j]);
                }
            }
#pragma unroll
            for (int j = 0; j < 4; j++)
                wmma::store_matrix_sync(&SP[(rt * 16) * SPD + (ct0 + j) * 16], sacc[j],
                                        SPD, wmma::mem_row_major);
        }
        __syncthreads();

        // ---- softmax ----
        for (int i = 0; i < 8; i++) {
            int r = warp * 8 + i;
            int li = r >> 3;
            float* Sr = &SP[r * SPD];
            __half* Pr = &Ph[r * PHD];
            float v0 = Sr[64 + lane] * 0.125f;
            float v1 = Sr[96 + lane] * 0.125f;
            float vs = (lane < 8) ? Sr[li * 8 + lane] * 0.125f : -3.4e38f;
            float mx = fmaxf(fmaxf(v0, v1), vs);
#pragma unroll
            for (int s = 16; s; s >>= 1) mx = fmaxf(mx, __shfl_xor_sync(0xffffffffu, mx, s));
            float e0 = __expf(v0 - mx), e1 = __expf(v1 - mx);
            float es = (lane < 8) ? __expf(vs - mx) : 0.f;
            float smv = e0 + e1 + es;
#pragma unroll
            for (int s = 16; s; s >>= 1) smv += __shfl_xor_sync(0xffffffffu, smv, s);
            float inv = 1.0f / smv;
            float p0 = e0 * inv, p1 = e1 * inv;
            size_t abase = OFF_TATT + ((size_t)(b * 8 + h) * 4096 + (size_t)(l0 + li0 + li) * 8 + (r & 7)) * 72;
            out[abase + 8 + lane]  = p0;
            out[abase + 40 + lane] = p1;
            float ps = es * inv;
            if (lane < 8) out[abase + lane] = ps;
            Pr[lane]      = __float2half_rn(0.f);
            Pr[32 + lane] = __float2half_rn(0.f);
            __syncwarp();
            Pr[64 + lane] = __float2half_rn(p0);
            Pr[96 + lane] = __float2half_rn(p1);
            if (lane < 8) Pr[li * 8 + lane] = __float2half_rn(ps);
        }
        __syncthreads();

        // ---- Out = P . Vst (64x64) ----
        {
            const int rt = warp >> 1;
            const int ct0 = (warp & 1) * 2;
            wmma::fragment<wmma::accumulator, 16, 16, 16, float> oacc[2];
#pragma unroll
            for (int j = 0; j < 2; j++) wmma::fill_fragment(oacc[j], 0.0f);
#pragma unroll
            for (int ks = 0; ks < 8; ks++) {
                wmma::fragment<wmma::matrix_a, 16, 16, 16, __half, wmma::row_major> af;
                wmma::load_matrix_sync(af, &Ph[(rt * 16) * PHD + ks * 16], PHD);
#pragma unroll
                for (int j = 0; j < 2; j++) {
                    wmma::fragment<wmma::matrix_b, 16, 16, 16, __half, wmma::row_major> bf;
                    wmma::load_matrix_sync(bf, &Vst[(ks * 16) * ST + (ct0 + j) * 16], ST);
                    wmma::mma_sync(oacc[j], af, bf, oacc[j]);
                }
            }
            const size_t g0 = (size_t)(b * 4104 + 8 + (l0 + li0) * 8 + rt * 16);
#pragma unroll
            for (int j = 0; j < 2; j++)
                wmma::store_matrix_sync(out + g0 * D_ + cb + (ct0 + j) * 16, oacc[j],
                                        D_, wmma::mem_row_major);
        }
        __syncthreads();
    }
}

// ============================================================================
// Others attention v6: register-tiled (1x4 jobs), fp16 scratch reads.
// Block = (m-chunk of 24, h, b). 256 threads.
// ============================================================================
constexpr int OKV = 68;  // float stride, float4-aligned
constexpr int OSS = 76;

__global__ __launch_bounds__(256) void others_attn_kernel(
    const float* __restrict__ bq, const float* __restrict__ bk,
    const float* __restrict__ bv, float* __restrict__ out)
{
    __shared__ float Qc[24][OKV];
    __shared__ float KV[72][OKV];
    __shared__ float S[24][OSS];
    __shared__ float bq_s[64], bk_s[64], bv_s[64];

    const int tid = threadIdx.x;
    const int m0 = blockIdx.x * 24;
    const int h = blockIdx.y, b = blockIdx.z;
    const int cb = h * DH_;

    if (tid < 64) {
        bq_s[tid] = bq[cb + tid];
        bk_s[tid] = bk[cb + tid];
        bv_s[tid] = bv[cb + tid];
    }
    __syncthreads();

    // stage K (+bk) and Q (+bq), 4 halves per job
    for (int idx = tid; idx < 72 * 16; idx += 256) {
        int n = idx >> 4, d0 = (idx & 15) * 4;
        uint2 raw = *reinterpret_cast<const uint2*>(&g_ss[1][(size_t)(b * SS_ + n) * D_ + cb + d0]);
        float2 f0 = __half22float2(*reinterpret_cast<__half2*>(&raw.x));
        float2 f1 = __half22float2(*reinterpret_cast<__half2*>(&raw.y));
        KV[n][d0]     = f0.x + bk_s[d0];
        KV[n][d0 + 1] = f0.y + bk_s[d0 + 1];
        KV[n][d0 + 2] = f1.x + bk_s[d0 + 2];
        KV[n][d0 + 3] = f1.y + bk_s[d0 + 3];
    }
    for (int idx = tid; idx < 24 * 16; idx += 256) {
        int i = idx >> 4, d0 = (idx & 15) * 4;
        uint2 raw = *reinterpret_cast<const uint2*>(&g_ss[0][(size_t)(b * SS_ + m0 + i) * D_ + cb + d0]);
        float2 f0 = __half22float2(*reinterpret_cast<__half2*>(&raw.x));
        float2 f1 = __half22float2(*reinterpret_cast<__half2*>(&raw.y));
        Qc[i][d0]     = f0.x + bq_s[d0];
        Qc[i][d0 + 1] = f0.y + bq_s[d0 + 1];
        Qc[i][d0 + 2] = f1.x + bq_s[d0 + 2];
        Qc[i][d0 + 3] = f1.y + bq_s[d0 + 3];
    }
    __syncthreads();

    // S[i][n0..n0+3] register-tiled: 24*18 = 432 jobs
    for (int e = tid; e < 432; e += 256) {
        int i = e / 18, n0 = (e - i * 18) * 4;
        float a0 = 0.f, a1 = 0.f, a2 = 0.f, a3 = 0.f;
#pragma unroll
        for (int d = 0; d < 64; d += 4) {
            float4 q = *reinterpret_cast<const float4*>(&Qc[i][d]);
            float4 k0 = *reinterpret_cast<const float4*>(&KV[n0][d]);
            float4 k1 = *reinterpret_cast<const float4*>(&KV[n0 + 1][d]);
            float4 k2 = *reinterpret_cast<const float4*>(&KV[n0 + 2][d]);
            float4 k3 = *reinterpret_cast<const float4*>(&KV[n0 + 3][d]);
            a0 = fmaf(q.x, k0.x, fmaf(q.y, k0.y, fmaf(q.z, k0.z, fmaf(q.w, k0.w, a0))));
            a1 = fmaf(q.x, k1.x, fmaf(q.y, k1.y, fmaf(q.z, k1.z, fmaf(q.w, k1.w, a1))));
            a2 = fmaf(q.x, k2.x, fmaf(q.y, k2.y, fmaf(q.z, k2.z, fmaf(q.w, k2.w, a2))));
            a3 = fmaf(q.x, k3.x, fmaf(q.y, k3.y, fmaf(q.z, k3.z, fmaf(q.w, k3.w, a3))));
        }
        float4 r = make_float4(a0 * 0.125f, a1 * 0.125f, a2 * 0.125f, a3 * 0.125f);
        *reinterpret_cast<float4*>(&S[i][n0]) = r;
    }
    __syncthreads();

    {
        int w = tid >> 5, lane = tid & 31;
        for (int i = w; i < 24; i += 8) {
            float v0 = S[i][lane];
            float v1 = S[i][lane + 32];
            float v2 = (lane < 8) ? S[i][lane + 64] : -3.4e38f;
            float mx = fmaxf(fmaxf(v0, v1), v2);
#pragma unroll
            for (int s = 16; s; s >>= 1) mx = fmaxf(mx, __shfl_xor_sync(0xffffffffu, mx, s));
            float e0 = __expf(v0 - mx), e1 = __expf(v1 - mx);
            float e2 = (lane < 8) ? __expf(v2 - mx) : 0.f;
            float smv = e0 + e1 + e2;
#pragma unroll
            for (int s = 16; s; s >>= 1) smv += __shfl_xor_sync(0xffffffffu, smv, s);
            float inv = 1.0f / smv;
            size_t abase = OFF_OATT + ((size_t)(b * 8 + h) * 72 + (m0 + i)) * 72;
            float p0 = e0 * inv, p1 = e1 * inv;
            S[i][lane] = p0;       out[abase + lane]      = p0;
            S[i][lane + 32] = p1;  out[abase + lane + 32] = p1;
            if (lane < 8) {
                float p2 = e2 * inv;
                S[i][lane + 64] = p2;
                out[abase + lane + 64] = p2;
            }
        }
    }
    __syncthreads();

    // reload KV with V (+bv)
    for (int idx = tid; idx < 72 * 16; idx += 256) {
        int n = idx >> 4, d0 = (idx & 15) * 4;
        uint2 raw = *reinterpret_cast<const uint2*>(&g_ss[2][(size_t)(b * SS_ + n) * D_ + cb + d0]);
        float2 f0 = __half22float2(*reinterpret_cast<__half2*>(&raw.x));
        float2 f1 = __half22float2(*reinterpret_cast<__half2*>(&raw.y));
        KV[n][d0]     = f0.x + bv_s[d0];
        KV[n][d0 + 1] = f0.y + bv_s[d0 + 1];
        KV[n][d0 + 2] = f1.x + bv_s[d0 + 2];
        KV[n][d0 + 3] = f1.y + bv_s[d0 + 3];
    }
    __syncthreads();

    // PV: out[i][d0..d0+3], 24*16 = 384 jobs
    for (int e = tid; e < 384; e += 256) {
        int i = e >> 4, d0 = (e & 15) * 4;
        float4 acc = make_float4(0.f, 0.f, 0.f, 0.f);
#pragma unroll
        for (int n = 0; n < 72; n += 4) {
            float4 p = *reinterpret_cast<const float4*>(&S[i][n]);
            float4 v0 = *reinterpret_cast<const float4*>(&KV[n][d0]);
            float4 v1 = *reinterpret_cast<const float4*>(&KV[n + 1][d0]);
            float4 v2 = *reinterpret_cast<const float4*>(&KV[n + 2][d0]);
            float4 v3 = *reinterpret_cast<const float4*>(&KV[n + 3][d0]);
            acc.x = fmaf(p.x, v0.x, fmaf(p.y, v1.x, fmaf(p.z, v2.x, fmaf(p.w, v3.x, acc.x))));
            acc.y = fmaf(p.x, v0.y, fmaf(p.y, v1.y, fmaf(p.z, v2.y, fmaf(p.w, v3.y, acc.y))));
            acc.z = fmaf(p.x, v0.z, fmaf(p.y, v1.z, fmaf(p.z, v2.z, fmaf(p.w, v3.z, acc.z))));
            acc.w = fmaf(p.x, v0.w, fmaf(p.y, v1.w, fmaf(p.z, v2.w, fmaf(p.w, v3.w, acc.w))));
        }
        int ng = m0 + i;
        int p = h * 4608 + ng * 64 + d0;
        int j = p >> 9;
        int c = p & 511;
        if (j < 8)
            *reinterpret_cast<float4*>(&out[(size_t)(b * 4104 + j) * D_ + c]) = acc;
        else
            *reinterpret_cast<float4*>(&out[OFF_OOUT + (size_t)(b * 64 + (j - 8)) * D_ + c]) = acc;
    }
}

// ============================================================================
extern "C" void kernel_launch(void* const* d_in, const int* in_sizes, int n_in,
                              void* d_out, int out_size)
{
    const float* Xt = (const float*)d_in[0];
    const float* Xo = (const float*)d_in[1];
    const float* Wq = (const float*)d_in[2];
    const float* bq = (const float*)d_in[3];
    const float* Wk = (const float*)d_in[4];
    const float* bk = (const float*)d_in[5];
    const float* Wv = (const float*)d_in[6];
    const float* bv = (const float*)d_in[7];
    float* out = (float*)d_out;

    cudaFuncSetAttribute((const void*)proj_gemm<0>, cudaFuncAttributeMaxDynamicSharedMemorySize, SMEM_PROJ);
    cudaFuncSetAttribute((const void*)proj_gemm<1>, cudaFuncAttributeMaxDynamicSharedMemorySize, SMEM_PROJ);
    cudaFuncSetAttribute((const void*)temporal_attn_kernel, cudaFuncAttributeMaxDynamicSharedMemorySize, SMEM_ATT);

    proj_gemm<0><<<dim3(NTT / P_BM, D_ / P_BN, 3), 512, SMEM_PROJ>>>(Xt, Xo, Wq, Wk, Wv);
    proj_gemm<1><<<dim3((NSS + P_BM - 1) / P_BM, D_ / P_BN, 3), 512, SMEM_PROJ>>>(Xt, Xo, Wq, Wk, Wv);
    temporal_attn_kernel<<<dim3(8, 8, 8), 256, SMEM_ATT>>>(bq, bk, bv, out);
    others_attn_kernel<<<dim3(3, 8, 8), 256>>>(bq, bk, bv, out);
}

// round 7
// speedup vs baseline: 1.0560x; 1.0560x over previous
#include <cuda_runtime.h>
#include <cuda_fp16.h>
#include <mma.h>

using namespace nvcuda;

// ---------------- problem constants ----------------
constexpr int B_  = 8;
constexpr int M_  = 8;
constexpr int D_  = 512;
constexpr int DH_ = 64;
constexpr int O_  = 64;
constexpr int SS_ = 72;    // M + O

constexpr int NTT = B_ * 512 * M_;  // 32768 temporal rows
constexpr int NSS = B_ * SS_;       // 576 ss rows

constexpr long long SZ_TOUT = (long long)B_ * 513 * M_ * D_;
constexpr long long SZ_OOUT = (long long)B_ * O_ * D_;
constexpr long long SZ_TATT = (long long)B_ * 8 * 512 * M_ * SS_;
constexpr long long OFF_OOUT = SZ_TOUT;
constexpr long long OFF_TATT = OFF_OOUT + SZ_OOUT;
constexpr long long OFF_OATT = OFF_TATT + SZ_TATT;

// ---------------- scratch (fp16) ----------------
__device__ __half g_tt[3][(size_t)NTT * D_];   // Qtt, Ktt, Vtt (no bias)
__device__ __half g_ss[3][(size_t)NSS * D_];   // Qss, Kss, Vss (no bias)

// ============================================================================
// Projection GEMM v7 (merged modes): fp16 WMMA m16n16k16, fp32 accumulate.
// BM=256 BN=128 BK=32, 512 threads / 16 warps (4x4), warp = 64x32.
// grid.x: [0,128) -> temporal-row tiles (mode 0); [128,131) -> ss-row tiles.
// ============================================================================
constexpr int P_BM = 256, P_BN = 128, P_BK = 32, P_LD = P_BK + 8;  // halves
constexpr int P_BUF = (P_BM + P_BN) * P_LD;
constexpr int SMEM_PROJ = 2 * P_BUF * 2;   // 61440 bytes
constexpr int NT0 = NTT / P_BM;            // 128 mode-0 tiles
constexpr int NT1 = 3;                     // ceil(576/256)

__global__ __launch_bounds__(512) void proj_gemm_all(
    const float* __restrict__ Xt, const float* __restrict__ Xo,
    const float* __restrict__ Wq, const float* __restrict__ Wk,
    const float* __restrict__ Wv)
{
    extern __shared__ __half smh[];

    const int tid  = threadIdx.x;
    const int warp = tid >> 5;
    const int lane = tid & 31;
    const int wr   = warp >> 2;
    const int wc   = warp & 3;
    const bool m0  = (blockIdx.x < NT0);
    const int tm   = m0 ? blockIdx.x : (blockIdx.x - NT0);
    const int tn   = blockIdx.y;
    const int mat  = blockIdx.z;

    const float* W   = (mat == 0) ? Wq : ((mat == 1) ? Wk : Wv);
    __half*      Out = m0 ? g_tt[mat] : g_ss[mat];
    const int  Mrows = m0 ? NTT : NSS;

    const int ar = tid >> 3;
    const int ac = (tid & 7) * 4;

    wmma::fragment<wmma::accumulator, 16, 16, 16, float> acc[4][2];
#pragma unroll
    for (int i = 0; i < 4; i++)
#pragma unroll
        for (int j = 0; j < 2; j++) wmma::fill_fragment(acc[i][j], 0.0f);

    float4 ra[4], rb[2];

    auto ldg = [&](int k0) {
#pragma unroll
        for (int i = 0; i < 4; i++) {
            int r  = ar + i * 64;
            int gr = tm * P_BM + r;
            float4 v = make_float4(0.f, 0.f, 0.f, 0.f);
            if (m0) {
                const float* src = Xt + (size_t)(gr + ((gr >> 12) << 3) + 8) * D_;
                v = *reinterpret_cast<const float4*>(src + k0 + ac);
            } else if (gr < NSS) {
                int bb = gr / SS_;
                int jj = gr - bb * SS_;
                const float* src = (jj < M_) ? (Xt + (size_t)(bb * 4104 + jj) * D_)
                                             : (Xo + (size_t)(bb * O_ + jj - M_) * D_);
                v = *reinterpret_cast<const float4*>(src + k0 + ac);
            }
            ra[i] = v;
        }
#pragma unroll
        for (int i = 0; i < 2; i++) {
            int r = ar + i * 64;
            rb[i] = *reinterpret_cast<const float4*>(W + (size_t)(tn * P_BN + r) * D_ + k0 + ac);
        }
    };

    auto sts = [&](int buf) {
        __half* As = smh + buf * P_BUF;
        __half* Bs = As + P_BM * P_LD;
#pragma unroll
        for (int i = 0; i < 4; i++) {
            union { uint2 u; __half2 h[2]; } pk;
            pk.h[0] = __floats2half2_rn(ra[i].x, ra[i].y);
            pk.h[1] = __floats2half2_rn(ra[i].z, ra[i].w);
            *reinterpret_cast<uint2*>(&As[(ar + i * 64) * P_LD + ac]) = pk.u;
        }
#pragma unroll
        for (int i = 0; i < 2; i++) {
            union { uint2 u; __half2 h[2]; } pk;
            pk.h[0] = __floats2half2_rn(rb[i].x, rb[i].y);
            pk.h[1] = __floats2half2_rn(rb[i].z, rb[i].w);
            *reinterpret_cast<uint2*>(&Bs[(ar + i * 64) * P_LD + ac]) = pk.u;
        }
    };

    ldg(0);
    sts(0);
    __syncthreads();

    for (int kt = 0; kt < D_ / P_BK; kt++) {
        if (kt + 1 < D_ / P_BK) ldg((kt + 1) * P_BK);

        const __half* As = smh + (kt & 1) * P_BUF;
        const __half* Bs = As + P_BM * P_LD;
#pragma unroll
        for (int kk = 0; kk < P_BK; kk += 16) {
            wmma::fragment<wmma::matrix_a, 16, 16, 16, __half, wmma::row_major> af[4];
            wmma::fragment<wmma::matrix_b, 16, 16, 16, __half, wmma::col_major> bf[2];
#pragma unroll
            for (int i = 0; i < 4; i++)
                wmma::load_matrix_sync(af[i], &As[(wr * 64 + i * 16) * P_LD + kk], P_LD);
#pragma unroll
            for (int j = 0; j < 2; j++)
                wmma::load_matrix_sync(bf[j], &Bs[(wc * 32 + j * 16) * P_LD + kk], P_LD);
#pragma unroll
            for (int i = 0; i < 4; i++)
#pragma unroll
                for (int j = 0; j < 2; j++)
                    wmma::mma_sync(acc[i][j], af[i], bf[j], acc[i][j]);
        }
        if (kt + 1 < D_ / P_BK) sts((kt + 1) & 1);
        __syncthreads();
    }

    // ---- epilogue: fp32 fragments -> smem patch -> fp16 gmem ----
    {
        float* pw = reinterpret_cast<float*>(smh) + warp * (16 * 20);
        const int pr = lane >> 1;
        const int pc = (lane & 1) * 8;
#pragma unroll
        for (int i = 0; i < 4; i++) {
            int row0 = tm * P_BM + wr * 64 + i * 16;
            if (row0 + 16 > Mrows) continue;
#pragma unroll
            for (int j = 0; j < 2; j++) {
                wmma::store_matrix_sync(pw, acc[i][j], 20, wmma::mem_row_major);
                __syncwarp();
                float4 a = *reinterpret_cast<const float4*>(&pw[pr * 20 + pc]);
                float4 b = *reinterpret_cast<const float4*>(&pw[pr * 20 + pc + 4]);
                union { uint4 u; __half2 h[4]; } pk;
                pk.h[0] = __floats2half2_rn(a.x, a.y);
                pk.h[1] = __floats2half2_rn(a.z, a.w);
                pk.h[2] = __floats2half2_rn(b.x, b.y);
                pk.h[3] = __floats2half2_rn(b.z, b.w);
                *reinterpret_cast<uint4*>(
                    &Out[(size_t)(row0 + pr) * D_ + tn * P_BN + wc * 32 + j * 16 + pc]) = pk.u;
                __syncwarp();
            }
        }
    }
}

// ============================================================================
// Temporal attention (v6, unchanged math) — launched LAST for ncu visibility.
// ============================================================================
constexpr int ST  = 72;
constexpr int SPD = 132;
constexpr int PHD = 136;
constexpr int SMEM_ATT =
    64 * ST * 2 + 128 * ST * 2 + 128 * ST * 2
  + 64 * SPD * 4 + 64 * PHD * 2 + 3 * 64 * 4;

__global__ __launch_bounds__(256) void temporal_attn_kernel(
    const float* __restrict__ bq, const float* __restrict__ bk,
    const float* __restrict__ bv, float* __restrict__ out)
{
    extern __shared__ char smc[];
    __half* Ql  = reinterpret_cast<__half*>(smc);
    __half* Kst = Ql  + 64 * ST;
    __half* Vst = Kst + 128 * ST;
    float*  SP  = reinterpret_cast<float*>(Vst + 128 * ST);
    __half* Ph  = reinterpret_cast<__half*>(SP + 64 * SPD);
    float*  bqs = reinterpret_cast<float*>(Ph + 64 * PHD);
    float*  bks = bqs + 64;
    float*  bvs = bks + 64;

    const int tid  = threadIdx.x;
    const int warp = tid >> 5;
    const int lane = tid & 31;
    const int b  = blockIdx.z, h = blockIdx.y;
    const int l0 = blockIdx.x * 64;
    const int cb = h * DH_;
    const int c4 = (tid & 15) * 4;

    if (tid < 64) {
        bqs[tid] = bq[cb + tid];
        bks[tid] = bk[cb + tid];
        bvs[tid] = bv[cb + tid];
    }
    __syncthreads();

    const __half2 bq01 = __floats2half2_rn(bqs[c4],     bqs[c4 + 1]);
    const __half2 bq23 = __floats2half2_rn(bqs[c4 + 2], bqs[c4 + 3]);
    const __half2 bk01 = __floats2half2_rn(bks[c4],     bks[c4 + 1]);
    const __half2 bk23 = __floats2half2_rn(bks[c4 + 2], bks[c4 + 3]);
    const __half2 bv01 = __floats2half2_rn(bvs[c4],     bvs[c4 + 1]);
    const __half2 bv23 = __floats2half2_rn(bvs[c4 + 2], bvs[c4 + 3]);

#pragma unroll
    for (int i = 0; i < 4; i++) {
        int idx = tid + i * 256;
        int o = idx >> 4;
        size_t srow = (size_t)(b * SS_ + 8 + o) * D_ + cb + c4;
        uint2 kr = *reinterpret_cast<const uint2*>(&g_ss[1][srow]);
        *reinterpret_cast<__half2*>(&Kst[(64 + o) * ST + c4])     = __hadd2(*reinterpret_cast<__half2*>(&kr.x), bk01);
        *reinterpret_cast<__half2*>(&Kst[(64 + o) * ST + c4 + 2]) = __hadd2(*reinterpret_cast<__half2*>(&kr.y), bk23);
        uint2 vr = *reinterpret_cast<const uint2*>(&g_ss[2][srow]);
        *reinterpret_cast<__half2*>(&Vst[(64 + o) * ST + c4])     = __hadd2(*reinterpret_cast<__half2*>(&vr.x), bv01);
        *reinterpret_cast<__half2*>(&Vst[(64 + o) * ST + c4 + 2]) = __hadd2(*reinterpret_cast<__half2*>(&vr.y), bv23);
    }
    __syncthreads();

    for (int li0 = 0; li0 < 64; li0 += 8) {
        const size_t rbase = (size_t)b * 4096 + (size_t)(l0 + li0) * 8;

#pragma unroll
        for (int i = 0; i < 4; i++) {
            int idx = tid + i * 256;
            int r = idx >> 4;
            size_t off = (rbase + r) * D_ + cb + c4;
            uint2 qr = *reinterpret_cast<const uint2*>(&g_tt[0][off]);
            *reinterpret_cast<__half2*>(&Ql[r * ST + c4])     = __hadd2(*reinterpret_cast<__half2*>(&qr.x), bq01);
            *reinterpret_cast<__half2*>(&Ql[r * ST + c4 + 2]) = __hadd2(*reinterpret_cast<__half2*>(&qr.y), bq23);
            uint2 kr = *reinterpret_cast<const uint2*>(&g_tt[1][off]);
            *reinterpret_cast<__half2*>(&Kst[r * ST + c4])     = __hadd2(*reinterpret_cast<__half2*>(&kr.x), bk01);
            *reinterpret_cast<__half2*>(&Kst[r * ST + c4 + 2]) = __hadd2(*reinterpret_cast<__half2*>(&kr.y), bk23);
            uint2 vr = *reinterpret_cast<const uint2*>(&g_tt[2][off]);
            *reinterpret_cast<__half2*>(&Vst[r * ST + c4])     = __hadd2(*reinterpret_cast<__half2*>(&vr.x), bv01);
            *reinterpret_cast<__half2*>(&Vst[r * ST + c4 + 2]) = __hadd2(*reinterpret_cast<__half2*>(&vr.y), bv23);
        }
        __syncthreads();

        {
            const int rt = warp >> 1;
            const int ct0 = (warp & 1) * 4;
            wmma::fragment<wmma::accumulator, 16, 16, 16, float> sacc[4];
#pragma unroll
            for (int j = 0; j < 4; j++) wmma::fill_fragment(sacc[j], 0.0f);
#pragma unroll
            for (int ks = 0; ks < 4; ks++) {
                wmma::fragment<wmma::matrix_a, 16, 16, 16, __half, wmma::row_major> af;
                wmma::load_matrix_sync(af, &Ql[(rt * 16) * ST + ks * 16], ST);
#pragma unroll
                for (int j = 0; j < 4; j++) {
                    wmma::fragment<wmma::matrix_b, 16, 16, 16, __half, wmma::col_major> bf;
                    wmma::load_matrix_sync(bf, &Kst[((ct0 + j) * 16) * ST + ks * 16], ST);
                    wmma::mma_sync(sacc[j], af, bf, sacc[j]);
                }
            }
#pragma unroll
            for (int j = 0; j < 4; j++)
                wmma::store_matrix_sync(&SP[(rt * 16) * SPD + (ct0 + j) * 16], sacc[j],
                                        SPD, wmma::mem_row_major);
        }
        __syncthreads();

        for (int i = 0; i < 8; i++) {
            int r = warp * 8 + i;
            int li = r >> 3;
            float* Sr = &SP[r * SPD];
            __half* Pr = &Ph[r * PHD];
            float v0 = Sr[64 + lane] * 0.125f;
            float v1 = Sr[96 + lane] * 0.125f;
            float vs = (lane < 8) ? Sr[li * 8 + lane] * 0.125f : -3.4e38f;
            float mx = fmaxf(fmaxf(v0, v1), vs);
#pragma unroll
            for (int s = 16; s; s >>= 1) mx = fmaxf(mx, __shfl_xor_sync(0xffffffffu, mx, s));
            float e0 = __expf(v0 - mx), e1 = __expf(v1 - mx);
            float es = (lane < 8) ? __expf(vs - mx) : 0.f;
            float smv = e0 + e1 + es;
#pragma unroll
            for (int s = 16; s; s >>= 1) smv += __shfl_xor_sync(0xffffffffu, smv, s);
            float inv = 1.0f / smv;
            float p0 = e0 * inv, p1 = e1 * inv;
            size_t abase = OFF_TATT + ((size_t)(b * 8 + h) * 4096 + (size_t)(l0 + li0 + li) * 8 + (r & 7)) * 72;
            out[abase + 8 + lane]  = p0;
            out[abase + 40 + lane] = p1;
            float ps = es * inv;
            if (lane < 8) out[abase + lane] = ps;
            Pr[lane]      = __float2half_rn(0.f);
            Pr[32 + lane] = __float2half_rn(0.f);
            __syncwarp();
            Pr[64 + lane] = __float2half_rn(p0);
            Pr[96 + lane] = __float2half_rn(p1);
            if (lane < 8) Pr[li * 8 + lane] = __float2half_rn(ps);
        }
        __syncthreads();

        {
            const int rt = warp >> 1;
            const int ct0 = (warp & 1) * 2;
            wmma::fragment<wmma::accumulator, 16, 16, 16, float> oacc[2];
#pragma unroll
            for (int j = 0; j < 2; j++) wmma::fill_fragment(oacc[j], 0.0f);
#pragma unroll
            for (int ks = 0; ks < 8; ks++) {
                wmma::fragment<wmma::matrix_a, 16, 16, 16, __half, wmma::row_major> af;
                wmma::load_matrix_sync(af, &Ph[(rt * 16) * PHD + ks * 16], PHD);
#pragma unroll
                for (int j = 0; j < 2; j++) {
                    wmma::fragment<wmma::matrix_b, 16, 16, 16, __half, wmma::row_major> bf;
                    wmma::load_matrix_sync(bf, &Vst[(ks * 16) * ST + (ct0 + j) * 16], ST);
                    wmma::mma_sync(oacc[j], af, bf, oacc[j]);
                }
            }
            const size_t g0 = (size_t)(b * 4104 + 8 + (l0 + li0) * 8 + rt * 16);
#pragma unroll
            for (int j = 0; j < 2; j++)
                wmma::store_matrix_sync(out + g0 * D_ + cb + (ct0 + j) * 16, oacc[j],
                                        D_, wmma::mem_row_major);
        }
        __syncthreads();
    }
}

// ============================================================================
// Others attention v7: lean R5 structure, fp16 scratch reads.
// ============================================================================
__global__ __launch_bounds__(256) void others_attn_kernel(
    const float* __restrict__ bq, const float* __restrict__ bk,
    const float* __restrict__ bv, float* __restrict__ out)
{
    __shared__ float Qc[24][65];
    __shared__ float KV[72][65];
    __shared__ float S[24][73];
    __shared__ float bq_s[64], bk_s[64], bv_s[64];

    const int tid = threadIdx.x;
    const int m0 = blockIdx.x * 24;
    const int h = blockIdx.y, b = blockIdx.z;
    const int cb = h * DH_;

    if (tid < 64) {
        bq_s[tid] = bq[cb + tid];
        bk_s[tid] = bk[cb + tid];
        bv_s[tid] = bv[cb + tid];
    }
    __syncthreads();

    for (int idx = tid; idx < 72 * 64; idx += 256) {
        int n = idx >> 6, d = idx & 63;
        KV[n][d] = __half2float(g_ss[1][(size_t)(b * SS_ + n) * D_ + cb + d]) + bk_s[d];
    }
    for (int idx = tid; idx < 24 * 64; idx += 256) {
        int i = idx >> 6, d = idx & 63;
        Qc[i][d] = __half2float(g_ss[0][(size_t)(b * SS_ + m0 + i) * D_ + cb + d]) + bq_s[d];
    }
    __syncthreads();

    for (int e = tid; e < 24 * 72; e += 256) {
        int i = e / 72, n = e - i * 72;
        float acc = 0.f;
#pragma unroll
        for (int d = 0; d < 64; d++) acc = fmaf(Qc[i][d], KV[n][d], acc);
        S[i][n] = acc * 0.125f;
    }
    __syncthreads();

    {
        int w = tid >> 5, lane = tid & 31;
        for (int i = w; i < 24; i += 8) {
            float v0 = S[i][lane];
            float v1 = S[i][lane + 32];
            float v2 = (lane < 8) ? S[i][lane + 64] : -3.4e38f;
            float mx = fmaxf(fmaxf(v0, v1), v2);
#pragma unroll
            for (int s = 16; s; s >>= 1) mx = fmaxf(mx, __shfl_xor_sync(0xffffffffu, mx, s));
            float e0 = __expf(v0 - mx), e1 = __expf(v1 - mx);
            float e2 = (lane < 8) ? __expf(v2 - mx) : 0.f;
            float smv = e0 + e1 + e2;
#pragma unroll
            for (int s = 16; s; s >>= 1) smv += __shfl_xor_sync(0xffffffffu, smv, s);
            float inv = 1.0f / smv;
            size_t abase = OFF_OATT + ((size_t)(b * 8 + h) * 72 + (m0 + i)) * 72;
            float p0 = e0 * inv, p1 = e1 * inv;
            S[i][lane] = p0;       out[abase + lane]      = p0;
            S[i][lane + 32] = p1;  out[abase + lane + 32] = p1;
            if (lane < 8) {
                float p2 = e2 * inv;
                S[i][lane + 64] = p2;
                out[abase + lane + 64] = p2;
            }
        }
    }
    __syncthreads();

    for (int idx = tid; idx < 72 * 64; idx += 256) {
        int n = idx >> 6, d = idx & 63;
        KV[n][d] = __half2float(g_ss[2][(size_t)(b * SS_ + n) * D_ + cb + d]) + bv_s[d];
    }
    __syncthreads();

    for (int e = tid; e < 24 * 64; e += 256) {
        int i = e >> 6, d = e & 63;
        float acc = 0.f;
#pragma unroll
        for (int n = 0; n < 72; n++) acc = fmaf(S[i][n], KV[n][d], acc);
        int ng = m0 + i;
        int p = h * 4608 + ng * 64 + d;
        int j = p >> 9;
        int c = p & 511;
        if (j < 8)
            out[(size_t)(b * 4104 + j) * D_ + c] = acc;
        else
            out[OFF_OOUT + (size_t)(b * 64 + (j - 8)) * D_ + c] = acc;
    }
}

// ============================================================================
extern "C" void kernel_launch(void* const* d_in, const int* in_sizes, int n_in,
                              void* d_out, int out_size)
{
    const float* Xt = (const float*)d_in[0];
    const float* Xo = (const float*)d_in[1];
    const float* Wq = (const float*)d_in[2];
    const float* bq = (const float*)d_in[3];
    const float* Wk = (const float*)d_in[4];
    const float* bk = (const float*)d_in[5];
    const float* Wv = (const float*)d_in[6];
    const float* bv = (const float*)d_in[7];
    float* out = (float*)d_out;

    cudaFuncSetAttribute((const void*)proj_gemm_all, cudaFuncAttributeMaxDynamicSharedMemorySize, SMEM_PROJ);
    cudaFuncSetAttribute((const void*)temporal_attn_kernel, cudaFuncAttributeMaxDynamicSharedMemorySize, SMEM_ATT);

    proj_gemm_all<<<dim3(NT0 + NT1, D_ / P_BN, 3), 512, SMEM_PROJ>>>(Xt, Xo, Wq, Wk, Wv);
    others_attn_kernel<<<dim3(3, 8, 8), 256>>>(bq, bk, bv, out);
    temporal_attn_kernel<<<dim3(8, 8, 8), 256, SMEM_ATT>>>(bq, bk, bv, out);
}

// round 8
// speedup vs baseline: 1.1147x; 1.0556x over previous
#include <cuda_runtime.h>
#include <cuda_fp16.h>
#include <mma.h>

using namespace nvcuda;

// ---------------- problem constants ----------------
constexpr int B_  = 8;
constexpr int M_  = 8;
constexpr int D_  = 512;
constexpr int DH_ = 64;
constexpr int O_  = 64;
constexpr int SS_ = 72;    // M + O

constexpr int NTT = B_ * 512 * M_;  // 32768 temporal rows
constexpr int NSS = B_ * SS_;       // 576 ss rows

constexpr long long SZ_TOUT = (long long)B_ * 513 * M_ * D_;
constexpr long long SZ_OOUT = (long long)B_ * O_ * D_;
constexpr long long SZ_TATT = (long long)B_ * 8 * 512 * M_ * SS_;
constexpr long long OFF_OOUT = SZ_TOUT;
constexpr long long OFF_TATT = OFF_OOUT + SZ_OOUT;
constexpr long long OFF_OATT = OFF_TATT + SZ_TATT;

// ---------------- scratch (fp16) ----------------
__device__ __half g_tt[3][(size_t)NTT * D_];   // Qtt, Ktt, Vtt (no bias)
__device__ __half g_ss[3][(size_t)NSS * D_];   // Qss, Kss, Vss (no bias)

// ============================================================================
// Projection GEMM v8: fp16 WMMA, warp tile 64x64 (2x MMA per fragment load).
// BM=128 BN=256 BK=32, 256 threads / 8 warps (2 rows x 4 cols of 64).
// Double-buffered smem. grid.x: [0,256) temporal tiles; [256,261) ss tiles.
// ============================================================================
constexpr int P_BM = 128, P_BN = 256, P_BK = 32, P_LD = P_BK + 8;  // halves
constexpr int P_BUF = (P_BM + P_BN) * P_LD;
constexpr int SMEM_PROJ = 2 * P_BUF * 2;   // 61440 bytes
constexpr int NT0 = NTT / P_BM;            // 256
constexpr int NT1 = (NSS + P_BM - 1) / P_BM;  // 5

__global__ __launch_bounds__(256) void proj_gemm_all(
    const float* __restrict__ Xt, const float* __restrict__ Xo,
    const float* __restrict__ Wq, const float* __restrict__ Wk,
    const float* __restrict__ Wv)
{
    extern __shared__ __half smh[];

    const int tid  = threadIdx.x;
    const int warp = tid >> 5;
    const int lane = tid & 31;
    const int wr   = warp >> 2;    // 0..1, 64-row strip
    const int wc   = warp & 3;     // 0..3, 64-col strip
    const bool md0 = (blockIdx.x < NT0);
    const int tm   = md0 ? blockIdx.x : (blockIdx.x - NT0);
    const int tn   = blockIdx.y;
    const int mat  = blockIdx.z;

    const float* W   = (mat == 0) ? Wq : ((mat == 1) ? Wk : Wv);
    __half*      Out = md0 ? g_tt[mat] : g_ss[mat];
    const int  Mrows = md0 ? NTT : NSS;

    const int ar = tid >> 3;          // 0..31
    const int ac = (tid & 7) * 4;

    wmma::fragment<wmma::accumulator, 16, 16, 16, float> acc[4][4];
#pragma unroll
    for (int i = 0; i < 4; i++)
#pragma unroll
        for (int j = 0; j < 4; j++) wmma::fill_fragment(acc[i][j], 0.0f);

    float4 ra[4], rb[8];

    auto ldg = [&](int k0) {
#pragma unroll
        for (int i = 0; i < 4; i++) {
            int r  = ar + i * 32;
            int gr = tm * P_BM + r;
            float4 v = make_float4(0.f, 0.f, 0.f, 0.f);
            if (md0) {
                const float* src = Xt + (size_t)(gr + ((gr >> 12) << 3) + 8) * D_;
                v = *reinterpret_cast<const float4*>(src + k0 + ac);
            } else if (gr < NSS) {
                int bb = gr / SS_;
                int jj = gr - bb * SS_;
                const float* src = (jj < M_) ? (Xt + (size_t)(bb * 4104 + jj) * D_)
                                             : (Xo + (size_t)(bb * O_ + jj - M_) * D_);
                v = *reinterpret_cast<const float4*>(src + k0 + ac);
            }
            ra[i] = v;
        }
#pragma unroll
        for (int i = 0; i < 8; i++) {
            int r = ar + i * 32;
            rb[i] = *reinterpret_cast<const float4*>(W + (size_t)(tn * P_BN + r) * D_ + k0 + ac);
        }
    };

    auto sts = [&](int buf) {
        __half* As = smh + buf * P_BUF;
        __half* Bs = As + P_BM * P_LD;
#pragma unroll
        for (int i = 0; i < 4; i++) {
            union { uint2 u; __half2 h[2]; } pk;
            pk.h[0] = __floats2half2_rn(ra[i].x, ra[i].y);
            pk.h[1] = __floats2half2_rn(ra[i].z, ra[i].w);
            *reinterpret_cast<uint2*>(&As[(ar + i * 32) * P_LD + ac]) = pk.u;
        }
#pragma unroll
        for (int i = 0; i < 8; i++) {
            union { uint2 u; __half2 h[2]; } pk;
            pk.h[0] = __floats2half2_rn(rb[i].x, rb[i].y);
            pk.h[1] = __floats2half2_rn(rb[i].z, rb[i].w);
            *reinterpret_cast<uint2*>(&Bs[(ar + i * 32) * P_LD + ac]) = pk.u;
        }
    };

    ldg(0);
    sts(0);
    __syncthreads();

    for (int kt = 0; kt < D_ / P_BK; kt++) {
        if (kt + 1 < D_ / P_BK) ldg((kt + 1) * P_BK);

        const __half* As = smh + (kt & 1) * P_BUF;
        const __half* Bs = As + P_BM * P_LD;
#pragma unroll
        for (int kk = 0; kk < P_BK; kk += 16) {
            wmma::fragment<wmma::matrix_a, 16, 16, 16, __half, wmma::row_major> af[4];
#pragma unroll
            for (int i = 0; i < 4; i++)
                wmma::load_matrix_sync(af[i], &As[(wr * 64 + i * 16) * P_LD + kk], P_LD);
#pragma unroll
            for (int j = 0; j < 4; j++) {
                wmma::fragment<wmma::matrix_b, 16, 16, 16, __half, wmma::col_major> bf;
                wmma::load_matrix_sync(bf, &Bs[(wc * 64 + j * 16) * P_LD + kk], P_LD);
#pragma unroll
                for (int i = 0; i < 4; i++)
                    wmma::mma_sync(acc[i][j], af[i], bf, acc[i][j]);
            }
        }
        if (kt + 1 < D_ / P_BK) sts((kt + 1) & 1);
        __syncthreads();
    }

    // ---- epilogue: fp32 fragments -> smem patch -> fp16 gmem ----
    {
        float* pw = reinterpret_cast<float*>(smh) + warp * (16 * 20);
        const int pr = lane >> 1;
        const int pc = (lane & 1) * 8;
#pragma unroll
        for (int i = 0; i < 4; i++) {
            int row0 = tm * P_BM + wr * 64 + i * 16;
            if (row0 + 16 > Mrows) continue;
#pragma unroll
            for (int j = 0; j < 4; j++) {
                wmma::store_matrix_sync(pw, acc[i][j], 20, wmma::mem_row_major);
                __syncwarp();
                float4 a = *reinterpret_cast<const float4*>(&pw[pr * 20 + pc]);
                float4 b = *reinterpret_cast<const float4*>(&pw[pr * 20 + pc + 4]);
                union { uint4 u; __half2 h[4]; } pk;
                pk.h[0] = __floats2half2_rn(a.x, a.y);
                pk.h[1] = __floats2half2_rn(a.z, a.w);
                pk.h[2] = __floats2half2_rn(b.x, b.y);
                pk.h[3] = __floats2half2_rn(b.z, b.w);
                *reinterpret_cast<uint4*>(
                    &Out[(size_t)(row0 + pr) * D_ + tn * P_BN + wc * 64 + j * 16 + pc]) = pk.u;
                __syncwarp();
            }
        }
    }
}

// ============================================================================
// Fused attention kernel. grid = (11, 8, 8), 256 threads.
//   blockIdx.x < 8  : temporal attention chunk (64 l's)
//   blockIdx.x >= 8 : others attention chunk (24 query rows)
// ============================================================================
constexpr int ST  = 72;
constexpr int SPD = 132;
constexpr int PHD = 136;
constexpr int SMEM_ATT =
    64 * ST * 2 + 128 * ST * 2 + 128 * ST * 2
  + 64 * SPD * 4 + 64 * PHD * 2 + 3 * 64 * 4;

__device__ __forceinline__ void temporal_attn_body(
    char* smc, const float* bq, const float* bk, const float* bv, float* out)
{
    __half* Ql  = reinterpret_cast<__half*>(smc);
    __half* Kst = Ql  + 64 * ST;
    __half* Vst = Kst + 128 * ST;
    float*  SP  = reinterpret_cast<float*>(Vst + 128 * ST);
    __half* Ph  = reinterpret_cast<__half*>(SP + 64 * SPD);
    float*  bqs = reinterpret_cast<float*>(Ph + 64 * PHD);
    float*  bks = bqs + 64;
    float*  bvs = bks + 64;

    const int tid  = threadIdx.x;
    const int warp = tid >> 5;
    const int lane = tid & 31;
    const int b  = blockIdx.z, h = blockIdx.y;
    const int l0 = blockIdx.x * 64;
    const int cb = h * DH_;
    const int c4 = (tid & 15) * 4;

    if (tid < 64) {
        bqs[tid] = bq[cb + tid];
        bks[tid] = bk[cb + tid];
        bvs[tid] = bv[cb + tid];
    }
    __syncthreads();

    const __half2 bq01 = __floats2half2_rn(bqs[c4],     bqs[c4 + 1]);
    const __half2 bq23 = __floats2half2_rn(bqs[c4 + 2], bqs[c4 + 3]);
    const __half2 bk01 = __floats2half2_rn(bks[c4],     bks[c4 + 1]);
    const __half2 bk23 = __floats2half2_rn(bks[c4 + 2], bks[c4 + 3]);
    const __half2 bv01 = __floats2half2_rn(bvs[c4],     bvs[c4 + 1]);
    const __half2 bv23 = __floats2half2_rn(bvs[c4 + 2], bvs[c4 + 3]);

#pragma unroll
    for (int i = 0; i < 4; i++) {
        int idx = tid + i * 256;
        int o = idx >> 4;
        size_t srow = (size_t)(b * SS_ + 8 + o) * D_ + cb + c4;
        uint2 kr = *reinterpret_cast<const uint2*>(&g_ss[1][srow]);
        *reinterpret_cast<__half2*>(&Kst[(64 + o) * ST + c4])     = __hadd2(*reinterpret_cast<__half2*>(&kr.x), bk01);
        *reinterpret_cast<__half2*>(&Kst[(64 + o) * ST + c4 + 2]) = __hadd2(*reinterpret_cast<__half2*>(&kr.y), bk23);
        uint2 vr = *reinterpret_cast<const uint2*>(&g_ss[2][srow]);
        *reinterpret_cast<__half2*>(&Vst[(64 + o) * ST + c4])     = __hadd2(*reinterpret_cast<__half2*>(&vr.x), bv01);
        *reinterpret_cast<__half2*>(&Vst[(64 + o) * ST + c4 + 2]) = __hadd2(*reinterpret_cast<__half2*>(&vr.y), bv23);
    }
    __syncthreads();

    for (int li0 = 0; li0 < 64; li0 += 8) {
        const size_t rbase = (size_t)b * 4096 + (size_t)(l0 + li0) * 8;

#pragma unroll
        for (int i = 0; i < 4; i++) {
            int idx = tid + i * 256;
            int r = idx >> 4;
            size_t off = (rbase + r) * D_ + cb + c4;
            uint2 qr = *reinterpret_cast<const uint2*>(&g_tt[0][off]);
            *reinterpret_cast<__half2*>(&Ql[r * ST + c4])     = __hadd2(*reinterpret_cast<__half2*>(&qr.x), bq01);
            *reinterpret_cast<__half2*>(&Ql[r * ST + c4 + 2]) = __hadd2(*reinterpret_cast<__half2*>(&qr.y), bq23);
            uint2 kr = *reinterpret_cast<const uint2*>(&g_tt[1][off]);
            *reinterpret_cast<__half2*>(&Kst[r * ST + c4])     = __hadd2(*reinterpret_cast<__half2*>(&kr.x), bk01);
            *reinterpret_cast<__half2*>(&Kst[r * ST + c4 + 2]) = __hadd2(*reinterpret_cast<__half2*>(&kr.y), bk23);
            uint2 vr = *reinterpret_cast<const uint2*>(&g_tt[2][off]);
            *reinterpret_cast<__half2*>(&Vst[r * ST + c4])     = __hadd2(*reinterpret_cast<__half2*>(&vr.x), bv01);
            *reinterpret_cast<__half2*>(&Vst[r * ST + c4 + 2]) = __hadd2(*reinterpret_cast<__half2*>(&vr.y), bv23);
        }
        __syncthreads();

        {
            const int rt = warp >> 1;
            const int ct0 = (warp & 1) * 4;
            wmma::fragment<wmma::accumulator, 16, 16, 16, float> sacc[4];
#pragma unroll
            for (int j = 0; j < 4; j++) wmma::fill_fragment(sacc[j], 0.0f);
#pragma unroll
            for (int ks = 0; ks < 4; ks++) {
                wmma::fragment<wmma::matrix_a, 16, 16, 16, __half, wmma::row_major> af;
                wmma::load_matrix_sync(af, &Ql[(rt * 16) * ST + ks * 16], ST);
#pragma unroll
                for (int j = 0; j < 4; j++) {
                    wmma::fragment<wmma::matrix_b, 16, 16, 16, __half, wmma::col_major> bf;
                    wmma::load_matrix_sync(bf, &Kst[((ct0 + j) * 16) * ST + ks * 16], ST);
                    wmma::mma_sync(sacc[j], af, bf, sacc[j]);
                }
            }
#pragma unroll
            for (int j = 0; j < 4; j++)
                wmma::store_matrix_sync(&SP[(rt * 16) * SPD + (ct0 + j) * 16], sacc[j],
                                        SPD, wmma::mem_row_major);
        }
        __syncthreads();

        for (int i = 0; i < 8; i++) {
            int r = warp * 8 + i;
            int li = r >> 3;
            float* Sr = &SP[r * SPD];
            __half* Pr = &Ph[r * PHD];
            float v0 = Sr[64 + lane] * 0.125f;
            float v1 = Sr[96 + lane] * 0.125f;
            float vs = (lane < 8) ? Sr[li * 8 + lane] * 0.125f : -3.4e38f;
            float mx = fmaxf(fmaxf(v0, v1), vs);
#pragma unroll
            for (int s = 16; s; s >>= 1) mx = fmaxf(mx, __shfl_xor_sync(0xffffffffu, mx, s));
            float e0 = __expf(v0 - mx), e1 = __expf(v1 - mx);
            float es = (lane < 8) ? __expf(vs - mx) : 0.f;
            float smv = e0 + e1 + es;
#pragma unroll
            for (int s = 16; s; s >>= 1) smv += __shfl_xor_sync(0xffffffffu, smv, s);
            float inv = 1.0f / smv;
            float p0 = e0 * inv, p1 = e1 * inv;
            size_t abase = OFF_TATT + ((size_t)(b * 8 + h) * 4096 + (size_t)(l0 + li0 + li) * 8 + (r & 7)) * 72;
            out[abase + 8 + lane]  = p0;
            out[abase + 40 + lane] = p1;
            float ps = es * inv;
            if (lane < 8) out[abase + lane] = ps;
            Pr[lane]      = __float2half_rn(0.f);
            Pr[32 + lane] = __float2half_rn(0.f);
            __syncwarp();
            Pr[64 + lane] = __float2half_rn(p0);
            Pr[96 + lane] = __float2half_rn(p1);
            if (lane < 8) Pr[li * 8 + lane] = __float2half_rn(ps);
        }
        __syncthreads();

        {
            const int rt = warp >> 1;
            const int ct0 = (warp & 1) * 2;
            wmma::fragment<wmma::accumulator, 16, 16, 16, float> oacc[2];
#pragma unroll
            for (int j = 0; j < 2; j++) wmma::fill_fragment(oacc[j], 0.0f);
#pragma unroll
            for (int ks = 0; ks < 8; ks++) {
                wmma::fragment<wmma::matrix_a, 16, 16, 16, __half, wmma::row_major> af;
                wmma::load_matrix_sync(af, &Ph[(rt * 16) * PHD + ks * 16], PHD);
#pragma unroll
                for (int j = 0; j < 2; j++) {
                    wmma::fragment<wmma::matrix_b, 16, 16, 16, __half, wmma::row_major> bf;
                    wmma::load_matrix_sync(bf, &Vst[(ks * 16) * ST + (ct0 + j) * 16], ST);
                    wmma::mma_sync(oacc[j], af, bf, oacc[j]);
                }
            }
            const size_t g0 = (size_t)(b * 4104 + 8 + (l0 + li0) * 8 + rt * 16);
#pragma unroll
            for (int j = 0; j < 2; j++)
                wmma::store_matrix_sync(out + g0 * D_ + cb + (ct0 + j) * 16, oacc[j],
                                        D_, wmma::mem_row_major);
        }
        __syncthreads();
    }
}

__device__ __forceinline__ void others_attn_body(
    char* smc, const float* bq, const float* bk, const float* bv, float* out)
{
    float* Qc  = reinterpret_cast<float*>(smc);   // [24][65]
    float* KV  = Qc + 24 * 65;                    // [72][65]
    float* S   = KV + 72 * 65;                    // [24][73]
    float* bq_s = S + 24 * 73;
    float* bk_s = bq_s + 64;
    float* bv_s = bk_s + 64;

    const int tid = threadIdx.x;
    const int m0 = (blockIdx.x - 8) * 24;
    const int h = blockIdx.y, b = blockIdx.z;
    const int cb = h * DH_;

    if (tid < 64) {
        bq_s[tid] = bq[cb + tid];
        bk_s[tid] = bk[cb + tid];
        bv_s[tid] = bv[cb + tid];
    }
    __syncthreads();

    for (int idx = tid; idx < 72 * 64; idx += 256) {
        int n = idx >> 6, d = idx & 63;
        KV[n * 65 + d] = __half2float(g_ss[1][(size_t)(b * SS_ + n) * D_ + cb + d]) + bk_s[d];
    }
    for (int idx = tid; idx < 24 * 64; idx += 256) {
        int i = idx >> 6, d = idx & 63;
        Qc[i * 65 + d] = __half2float(g_ss[0][(size_t)(b * SS_ + m0 + i) * D_ + cb + d]) + bq_s[d];
    }
    __syncthreads();

    for (int e = tid; e < 24 * 72; e += 256) {
        int i = e / 72, n = e - i * 72;
        float acc = 0.f;
#pragma unroll
        for (int d = 0; d < 64; d++) acc = fmaf(Qc[i * 65 + d], KV[n * 65 + d], acc);
        S[i * 73 + n] = acc * 0.125f;
    }
    __syncthreads();

    {
        int w = tid >> 5, lane = tid & 31;
        for (int i = w; i < 24; i += 8) {
            float v0 = S[i * 73 + lane];
            float v1 = S[i * 73 + lane + 32];
            float v2 = (lane < 8) ? S[i * 73 + lane + 64] : -3.4e38f;
            float mx = fmaxf(fmaxf(v0, v1), v2);
#pragma unroll
            for (int s = 16; s; s >>= 1) mx = fmaxf(mx, __shfl_xor_sync(0xffffffffu, mx, s));
            float e0 = __expf(v0 - mx), e1 = __expf(v1 - mx);
            float e2 = (lane < 8) ? __expf(v2 - mx) : 0.f;
            float smv = e0 + e1 + e2;
#pragma unroll
            for (int s = 16; s; s >>= 1) smv += __shfl_xor_sync(0xffffffffu, smv, s);
            float inv = 1.0f / smv;
            size_t abase = OFF_OATT + ((size_t)(b * 8 + h) * 72 + (m0 + i)) * 72;
            float p0 = e0 * inv, p1 = e1 * inv;
            S[i * 73 + lane] = p0;       out[abase + lane]      = p0;
            S[i * 73 + lane + 32] = p1;  out[abase + lane + 32] = p1;
            if (lane < 8) {
                float p2 = e2 * inv;
                S[i * 73 + lane + 64] = p2;
                out[abase + lane + 64] = p2;
            }
        }
    }
    __syncthreads();

    for (int idx = tid; idx < 72 * 64; idx += 256) {
        int n = idx >> 6, d = idx & 63;
        KV[n * 65 + d] = __half2float(g_ss[2][(size_t)(b * SS_ + n) * D_ + cb + d]) + bv_s[d];
    }
    __syncthreads();

    for (int e = tid; e < 24 * 64; e += 256) {
        int i = e >> 6, d = e & 63;
        float acc = 0.f;
#pragma unroll
        for (int n = 0; n < 72; n++) acc = fmaf(S[i * 73 + n], KV[n * 65 + d], acc);
        int ng = m0 + i;
        int p = h * 4608 + ng * 64 + d;
        int j = p >> 9;
        int c = p & 511;
        if (j < 8)
            out[(size_t)(b * 4104 + j) * D_ + c] = acc;
        else
            out[OFF_OOUT + (size_t)(b * 64 + (j - 8)) * D_ + c] = acc;
    }
}

__global__ __launch_bounds__(256) void attn_fused_kernel(
    const float* __restrict__ bq, const float* __restrict__ bk,
    const float* __restrict__ bv, float* __restrict__ out)
{
    extern __shared__ char smc[];
    if (blockIdx.x < 8)
        temporal_attn_body(smc, bq, bk, bv, out);
    else
        others_attn_body(smc, bq, bk, bv, out);
}

// ============================================================================
extern "C" void kernel_launch(void* const* d_in, const int* in_sizes, int n_in,
                              void* d_out, int out_size)
{
    const float* Xt = (const float*)d_in[0];
    const float* Xo = (const float*)d_in[1];
    const float* Wq = (const float*)d_in[2];
    const float* bq = (const float*)d_in[3];
    const float* Wk = (const float*)d_in[4];
    const float* bk = (const float*)d_in[5];
    const float* Wv = (const float*)d_in[6];
    const float* bv = (const float*)d_in[7];
    float* out = (float*)d_out;

    cudaFuncSetAttribute((const void*)proj_gemm_all, cudaFuncAttributeMaxDynamicSharedMemorySize, SMEM_PROJ);
    cudaFuncSetAttribute((const void*)attn_fused_kernel, cudaFuncAttributeMaxDynamicSharedMemorySize, SMEM_ATT);

    proj_gemm_all<<<dim3(NT0 + NT1, D_ / P_BN, 3), 256, SMEM_PROJ>>>(Xt, Xo, Wq, Wk, Wv);
    attn_fused_kernel<<<dim3(11, 8, 8), 256, SMEM_ATT>>>(bq, bk, bv, out);
}